// round 16
// baseline (speedup 1.0000x reference)
#include <cuda_runtime.h>
#include <cuda_bf16.h>
#include <cuda_fp16.h>
#include <cstddef>
#include <cstdint>

#define NN 100000
#define NE 1600000
#define NG 512
#define HD 128
#define HD2 256
#define KW (HD / 2)          // 64 packed kpair words per node row
#define SCAN_B 1024
#define SCAN_NB ((NN + SCAN_B - 1) / SCAN_B)   // 98

// ---------------- scratch (static device allocations) ----------------
__device__ __half g_post[(size_t)NN * HD];     // fp16 activations (gather input)
__device__ unsigned g_hhi[(size_t)NN * KW];    // gather output, bf16 hi plane (packed x2)
__device__ unsigned g_hlo[(size_t)NN * KW];    // gather output, bf16 lo plane
__device__ float g_t[(size_t)NN * HD2];
__device__ float g_y[(size_t)NN * HD];
__device__ float g_stats[16][HD2];
__device__ float g_scale[HD2];
__device__ float g_shift[HD2];
__device__ float g_vfeat[NG * HD];
__device__ float g_pooled[NG * HD];
__device__ float g_zmid[NG * HD2];
__device__ float g_cnt[NG];
__device__ int g_deg[NN];
__device__ int g_rowptr[NN];
__device__ int g_cursor[NN];
__device__ int g_eidx[NE];
__device__ int g_aux[SCAN_NB];
// pre-split weights: 6 matrices, packed bf16x2, word index kp*N + n
__device__ unsigned g_whi[98304];
__device__ unsigned g_wlo[98304];

// ---------------- helpers ----------------
__device__ __forceinline__ void red_add_v4(float* p, float4 v) {
    asm volatile("red.global.add.v4.f32 [%0], {%1,%2,%3,%4};"
                 :: "l"(p), "f"(v.x), "f"(v.y), "f"(v.z), "f"(v.w)
                 : "memory");
}

__device__ __forceinline__ void bsplit2(float a, float b, unsigned& h, unsigned& l) {
    unsigned ha = __bfloat16_as_ushort(__float2bfloat16_rn(a));
    unsigned hb = __bfloat16_as_ushort(__float2bfloat16_rn(b));
    float fa = __uint_as_float(ha << 16);
    float fb = __uint_as_float(hb << 16);
    unsigned la = __bfloat16_as_ushort(__float2bfloat16_rn(a - fa));
    unsigned lb = __bfloat16_as_ushort(__float2bfloat16_rn(b - fb));
    h = ha | (hb << 16);
    l = la | (lb << 16);
}

__device__ __forceinline__ void mma_bf16(float* c, const unsigned* a, const unsigned* b) {
    asm volatile(
        "mma.sync.aligned.m16n8k16.row.col.f32.bf16.bf16.f32 "
        "{%0,%1,%2,%3}, {%4,%5,%6,%7}, {%8,%9}, {%0,%1,%2,%3};"
        : "+f"(c[0]), "+f"(c[1]), "+f"(c[2]), "+f"(c[3])
        : "r"(a[0]), "r"(a[1]), "r"(a[2]), "r"(a[3]), "r"(b[0]), "r"(b[1]));
}

__device__ __forceinline__ void bn_coef(float s, float q, float gamma, float beta,
                                        float invM, float& sc, float& sh) {
    float mu = s * invM;
    float var = q * invM - mu * mu;
    float t = gamma * rsqrtf(var + 1e-5f);
    sc = t;
    sh = fmaf(-mu, t, beta);
}

// ================= x -> fp16 conversion (into the post buffer) =================
__global__ void k_x2h(const float* __restrict__ x, __half* __restrict__ xh) {
    int i = blockIdx.x * blockDim.x + threadIdx.x;
    if (i >= NN * (HD / 4)) return;
    float4 v = *(const float4*)(x + (size_t)i * 4);
    __half2 p0 = __floats2half2_rn(v.x, v.y);
    __half2 p1 = __floats2half2_rn(v.z, v.w);
    *(uint2*)(xh + (size_t)i * 4) = make_uint2(*(unsigned*)&p0, *(unsigned*)&p1);
}

// ================= fused weight pre-split (all 6 matrices) =================
__global__ void k_wsplit_all(const float* __restrict__ c1W1, const float* __restrict__ c1W2,
                             const float* __restrict__ cW1, const float* __restrict__ cW2,
                             unsigned* __restrict__ hi, unsigned* __restrict__ lo) {
    int i = blockIdx.x * blockDim.x + threadIdx.x;
    if (i >= 6 * 16384) return;
    int seg = i >> 14;
    int w = i & 16383;
    const float* W;
    int N;
    switch (seg) {
        case 0: W = c1W1; N = HD2; break;
        case 1: W = c1W2; N = HD; break;
        case 2: W = cW1; N = HD2; break;
        case 3: W = cW2; N = HD; break;
        case 4: W = cW1 + (size_t)HD * HD2; N = HD2; break;
        default: W = cW2 + (size_t)HD2 * HD; N = HD; break;
    }
    int kp = w / N, n = w - kp * N;
    float a = W[(size_t)(2 * kp) * N + n];
    float b = W[(size_t)(2 * kp + 1) * N + n];
    bsplit2(a, b, hi[i], lo[i]);
}

// ================= CSR build =================
__global__ void k_hist(const int* __restrict__ dst, int* __restrict__ deg) {
    int e = blockIdx.x * blockDim.x + threadIdx.x;
    if (e < NE) atomicAdd(&deg[__ldg(dst + e)], 1);
}

__global__ void k_scan1(const int* __restrict__ deg, int* __restrict__ rowptr,
                        int* __restrict__ aux) {
    __shared__ int s[SCAN_B];
    int t = threadIdx.x;
    int i = blockIdx.x * SCAN_B + t;
    int v = (i < NN) ? deg[i] : 0;
    s[t] = v;
    __syncthreads();
    for (int off = 1; off < SCAN_B; off <<= 1) {
        int add = (t >= off) ? s[t - off] : 0;
        __syncthreads();
        s[t] += add;
        __syncthreads();
    }
    if (i < NN) rowptr[i] = s[t] - v;
    if (t == SCAN_B - 1) aux[blockIdx.x] = s[t];
}

__global__ void k_scan2(int* __restrict__ aux) {
    __shared__ int s[128];
    int t = threadIdx.x;
    int v = (t < SCAN_NB) ? aux[t] : 0;
    s[t] = v;
    __syncthreads();
    for (int off = 1; off < 128; off <<= 1) {
        int add = (t >= off) ? s[t - off] : 0;
        __syncthreads();
        s[t] += add;
        __syncthreads();
    }
    if (t < SCAN_NB) aux[t] = s[t] - v;
}

__global__ void k_scan3(int* __restrict__ rowptr, const int* __restrict__ aux,
                        int* __restrict__ cursor) {
    int i = blockIdx.x * SCAN_B + threadIdx.x;
    if (i < NN) {
        int v = rowptr[i] + aux[blockIdx.x];
        rowptr[i] = v;
        cursor[i] = v;
    }
}

__global__ void k_fill(const int* __restrict__ src, const int* __restrict__ dst,
                       int* __restrict__ cursor, int* __restrict__ eidx) {
    int e = blockIdx.x * blockDim.x + threadIdx.x;
    if (e >= NE) return;
    int pos = atomicAdd(&cursor[__ldg(dst + e)], 1);
    eidx[pos] = __ldg(src + e);
}

// ====== gather (fp16 input, half-warp per node) -> pre-split bf16 planes ======
// 2 nodes per warp; 16 lanes x uint4 (8 halves = 4 kpairs) per row.
// Epilogue splits the fp32 accumulators into bf16 hi/lo planes (GEMM1 operand).
__global__ void k_gather_h(const __half* __restrict__ in, const int* __restrict__ rowptr,
                           const int* __restrict__ deg, const int* __restrict__ eidx,
                           unsigned* __restrict__ ohi, unsigned* __restrict__ olo) {
    int warp = (blockIdx.x * blockDim.x + threadIdx.x) >> 5;
    if (warp * 2 >= NN) return;               // NN even -> warps are full
    int lane = threadIdx.x & 31;
    int hw = lane >> 4;
    int l16 = lane & 15;
    int n = warp * 2 + hw;

    float acc[8];
    {
        uint4 u = *(const uint4*)(in + (size_t)n * HD + l16 * 8);
        const __half2* hp = (const __half2*)&u;
#pragma unroll
        for (int k = 0; k < 4; k++) {
            float2 f = __half22float2(hp[k]);
            acc[2 * k] = f.x;
            acc[2 * k + 1] = f.y;
        }
    }
    int start = __ldg(rowptr + n);
    int d = __ldg(deg + n);
    int dmax = max(d, __shfl_xor_sync(0xffffffffu, d, 16));
    for (int base = 0; base < dmax; base += 16) {
        int idx = 0;
        if (base + l16 < d) idx = __ldg(eidx + start + base + l16);
        int cnt = min(16, dmax - base);
#pragma unroll 4
        for (int j = 0; j < cnt; j++) {
            int s = __shfl_sync(0xffffffffu, idx, hw * 16 + j);
            if (base + j < d) {
                uint4 u = *(const uint4*)(in + (size_t)s * HD + l16 * 8);
                const __half2* hp = (const __half2*)&u;
#pragma unroll
                for (int k = 0; k < 4; k++) {
                    float2 f = __half22float2(hp[k]);
                    acc[2 * k] += f.x;
                    acc[2 * k + 1] += f.y;
                }
            }
        }
    }
    uint4 uh, ul;
    bsplit2(acc[0], acc[1], uh.x, ul.x);
    bsplit2(acc[2], acc[3], uh.y, ul.y);
    bsplit2(acc[4], acc[5], uh.z, ul.z);
    bsplit2(acc[6], acc[7], uh.w, ul.w);
    size_t wo = (size_t)n * KW + l16 * 4;
    *(uint4*)(ohi + wo) = uh;
    *(uint4*)(olo + wo) = ul;
}

// ------- GEMM1: pre-split A planes (no prologue), fused column-stats epilogue -------
// A given as bf16 hi/lo packed-kpair planes (row-major, KW words per row).
__global__ void __launch_bounds__(256, 2) k_gemm_bfp(
    const unsigned* __restrict__ Ahi, const unsigned* __restrict__ Alo,
    const unsigned* __restrict__ Bhi, const unsigned* __restrict__ Blo,
    const float* __restrict__ bias,
    float* __restrict__ C, float* __restrict__ gsum, float* __restrict__ gsq,
    int M, int K, int N) {
    __shared__ unsigned As_hi[2][128][12];
    __shared__ unsigned As_lo[2][128][12];
    __shared__ unsigned Bs_hi[2][8][136];
    __shared__ unsigned Bs_lo[2][8][136];
    __shared__ float s_sum[128];
    __shared__ float s_sq[128];

    const int tid = threadIdx.x;
    const int wid = tid >> 5;
    const int lane = tid & 31;
    const int g = lane >> 2;
    const int tg = lane & 3;
    const int warp_m = wid >> 1;
    const int warp_n = wid & 1;
    const int row0 = blockIdx.y * 128;
    const int col0 = blockIdx.x * 128;
    const int Kw = K >> 1;

    if (tid < 128) { s_sum[tid] = 0.f; s_sq[tid] = 0.f; }

    float acc[2][8][4];
#pragma unroll
    for (int mt = 0; mt < 2; mt++)
#pragma unroll
        for (int nt = 0; nt < 8; nt++)
#pragma unroll
            for (int i = 0; i < 4; i++) acc[mt][nt][i] = 0.f;

    const int a_r0 = tid >> 2;
    const int a_r1 = a_r0 + 64;
    const int a_kp = (tid & 3) * 2;
    const int b_kr = tid >> 5;
    const int b_c4 = (tid & 31) * 4;

    auto loadArow = [&](int kc, int r, uint2& ph, uint2& pl) {
        int grow = row0 + r;
        if (grow < M) {
            size_t wo = (size_t)grow * Kw + (kc >> 1) + a_kp;
            ph = *(const uint2*)(Ahi + wo);
            pl = *(const uint2*)(Alo + wo);
        } else {
            ph = make_uint2(0u, 0u);
            pl = make_uint2(0u, 0u);
        }
    };

    uint2 ph0, pl0, ph1, pl1;
    loadArow(0, a_r0, ph0, pl0);
    loadArow(0, a_r1, ph1, pl1);
    uint4 pbh = *(const uint4*)(Bhi + (size_t)b_kr * N + col0 + b_c4);
    uint4 pbl = *(const uint4*)(Blo + (size_t)b_kr * N + col0 + b_c4);
    *(uint2*)&As_hi[0][a_r0][a_kp] = ph0;
    *(uint2*)&As_lo[0][a_r0][a_kp] = pl0;
    *(uint2*)&As_hi[0][a_r1][a_kp] = ph1;
    *(uint2*)&As_lo[0][a_r1][a_kp] = pl1;
    *(uint4*)&Bs_hi[0][b_kr][b_c4] = pbh;
    *(uint4*)&Bs_lo[0][b_kr][b_c4] = pbl;
    __syncthreads();

    const int niter = K >> 4;
    for (int it = 0; it < niter; it++) {
        int st = it & 1;
        bool more = (it + 1 < niter);
        if (more) {
            int kc = (it + 1) << 4;
            loadArow(kc, a_r0, ph0, pl0);
            loadArow(kc, a_r1, ph1, pl1);
            size_t boff = (size_t)((kc >> 1) + b_kr) * N + col0 + b_c4;
            pbh = *(const uint4*)(Bhi + boff);
            pbl = *(const uint4*)(Blo + boff);
        }
        unsigned ah[2][4], al[2][4];
#pragma unroll
        for (int mt = 0; mt < 2; mt++) {
            int r = warp_m * 32 + mt * 16;
            ah[mt][0] = As_hi[st][r + g][tg];
            ah[mt][1] = As_hi[st][r + g + 8][tg];
            ah[mt][2] = As_hi[st][r + g][4 + tg];
            ah[mt][3] = As_hi[st][r + g + 8][4 + tg];
            al[mt][0] = As_lo[st][r + g][tg];
            al[mt][1] = As_lo[st][r + g + 8][tg];
            al[mt][2] = As_lo[st][r + g][4 + tg];
            al[mt][3] = As_lo[st][r + g + 8][4 + tg];
        }
#pragma unroll
        for (int nt = 0; nt < 8; nt++) {
            int n = warp_n * 64 + nt * 8;
            unsigned bh[2], bl[2];
            bh[0] = Bs_hi[st][tg][n + g];
            bh[1] = Bs_hi[st][4 + tg][n + g];
            bl[0] = Bs_lo[st][tg][n + g];
            bl[1] = Bs_lo[st][4 + tg][n + g];
#pragma unroll
            for (int mt = 0; mt < 2; mt++) {
                mma_bf16(acc[mt][nt], ah[mt], bh);
                mma_bf16(acc[mt][nt], al[mt], bh);
                mma_bf16(acc[mt][nt], ah[mt], bl);
            }
        }
        if (more) {
            int ns = st ^ 1;
            *(uint2*)&As_hi[ns][a_r0][a_kp] = ph0;
            *(uint2*)&As_lo[ns][a_r0][a_kp] = pl0;
            *(uint2*)&As_hi[ns][a_r1][a_kp] = ph1;
            *(uint2*)&As_lo[ns][a_r1][a_kp] = pl1;
            *(uint4*)&Bs_hi[ns][b_kr][b_c4] = pbh;
            *(uint4*)&Bs_lo[ns][b_kr][b_c4] = pbl;
        }
        __syncthreads();
    }

    float cs[8][2], cq[8][2];
#pragma unroll
    for (int nt = 0; nt < 8; nt++) {
        cs[nt][0] = cs[nt][1] = 0.f;
        cq[nt][0] = cq[nt][1] = 0.f;
    }
#pragma unroll
    for (int mt = 0; mt < 2; mt++) {
        int r_lo = row0 + warp_m * 32 + mt * 16 + g;
#pragma unroll
        for (int nt = 0; nt < 8; nt++) {
            int c = col0 + warp_n * 64 + nt * 8 + tg * 2;
            float2 bb = *(const float2*)(bias + c);
            if (r_lo < M) {
                float o0 = acc[mt][nt][0] + bb.x;
                float o1 = acc[mt][nt][1] + bb.y;
                *(float2*)(C + (size_t)r_lo * N + c) = make_float2(o0, o1);
                cs[nt][0] += o0; cq[nt][0] = fmaf(o0, o0, cq[nt][0]);
                cs[nt][1] += o1; cq[nt][1] = fmaf(o1, o1, cq[nt][1]);
            }
            if (r_lo + 8 < M) {
                float o2 = acc[mt][nt][2] + bb.x;
                float o3 = acc[mt][nt][3] + bb.y;
                *(float2*)(C + (size_t)(r_lo + 8) * N + c) = make_float2(o2, o3);
                cs[nt][0] += o2; cq[nt][0] = fmaf(o2, o2, cq[nt][0]);
                cs[nt][1] += o3; cq[nt][1] = fmaf(o3, o3, cq[nt][1]);
            }
        }
    }
#pragma unroll
    for (int nt = 0; nt < 8; nt++) {
#pragma unroll
        for (int c2 = 0; c2 < 2; c2++) {
            float v = cs[nt][c2], q = cq[nt][c2];
            v += __shfl_xor_sync(0xffffffff, v, 16);
            q += __shfl_xor_sync(0xffffffff, q, 16);
            v += __shfl_xor_sync(0xffffffff, v, 8);
            q += __shfl_xor_sync(0xffffffff, q, 8);
            v += __shfl_xor_sync(0xffffffff, v, 4);
            q += __shfl_xor_sync(0xffffffff, q, 4);
            if (g == 0) {
                int cl = warp_n * 64 + nt * 8 + tg * 2 + c2;
                atomicAdd(&s_sum[cl], v);
                atomicAdd(&s_sq[cl], q);
            }
        }
    }
    __syncthreads();
    if (tid < 128) {
        atomicAdd(&gsum[col0 + tid], s_sum[tid]);
        atomicAdd(&gsq[col0 + tid], s_sq[tid]);
    }
}

// ------- GEMM2: fp32 A with in-block BN prologue + split (unchanged from R15) -------
__global__ void __launch_bounds__(256, 2) k_gemm_bf(
    const float* __restrict__ A, const unsigned* __restrict__ Bhi,
    const unsigned* __restrict__ Blo, const float* __restrict__ bias,
    const float* __restrict__ sumIn, const float* __restrict__ sqIn,
    const float* __restrict__ gamma, const float* __restrict__ beta, float invM,
    float* __restrict__ C, float* __restrict__ gsum, float* __restrict__ gsq,
    int M, int K, int N) {
    __shared__ unsigned As_hi[2][128][12];
    __shared__ unsigned As_lo[2][128][12];
    __shared__ unsigned Bs_hi[2][8][136];
    __shared__ unsigned Bs_lo[2][8][136];
    __shared__ float s_sum[128];
    __shared__ float s_sq[128];
    __shared__ float sc_s[HD2];
    __shared__ float sh_s[HD2];

    const int tid = threadIdx.x;
    const int wid = tid >> 5;
    const int lane = tid & 31;
    const int g = lane >> 2;
    const int tg = lane & 3;
    const int warp_m = wid >> 1;
    const int warp_n = wid & 1;
    const int row0 = blockIdx.y * 128;
    const int col0 = blockIdx.x * 128;

    if (tid < 128) { s_sum[tid] = 0.f; s_sq[tid] = 0.f; }
    for (int c = tid; c < K; c += 256)
        bn_coef(sumIn[c], sqIn[c], gamma[c], beta[c], invM, sc_s[c], sh_s[c]);
    __syncthreads();

    float acc[2][8][4];
#pragma unroll
    for (int mt = 0; mt < 2; mt++)
#pragma unroll
        for (int nt = 0; nt < 8; nt++)
#pragma unroll
            for (int i = 0; i < 4; i++) acc[mt][nt][i] = 0.f;

    const int a_r0 = tid >> 2;
    const int a_r1 = a_r0 + 64;
    const int a_q = (tid & 3) * 4;
    const int a_kp = (tid & 3) * 2;
    const int b_kr = tid >> 5;
    const int b_c4 = (tid & 31) * 4;

    auto loadA = [&](int kc, int r) -> float4 {
        int grow = row0 + r;
        float4 v = make_float4(0.f, 0.f, 0.f, 0.f);
        if (grow < M) v = *(const float4*)(A + (size_t)grow * K + kc + a_q);
        v.x = fmaxf(fmaf(v.x, sc_s[kc + a_q + 0], sh_s[kc + a_q + 0]), 0.f);
        v.y = fmaxf(fmaf(v.y, sc_s[kc + a_q + 1], sh_s[kc + a_q + 1]), 0.f);
        v.z = fmaxf(fmaf(v.z, sc_s[kc + a_q + 2], sh_s[kc + a_q + 2]), 0.f);
        v.w = fmaxf(fmaf(v.w, sc_s[kc + a_q + 3], sh_s[kc + a_q + 3]), 0.f);
        return v;
    };
    auto storeA = [&](int st, int r, float4 v) {
        unsigned h01, l01, h23, l23;
        bsplit2(v.x, v.y, h01, l01);
        bsplit2(v.z, v.w, h23, l23);
        *(uint2*)&As_hi[st][r][a_kp] = make_uint2(h01, h23);
        *(uint2*)&As_lo[st][r][a_kp] = make_uint2(l01, l23);
    };

    float4 pa0 = loadA(0, a_r0);
    float4 pa1 = loadA(0, a_r1);
    uint4 pbh = *(const uint4*)(Bhi + (size_t)b_kr * N + col0 + b_c4);
    uint4 pbl = *(const uint4*)(Blo + (size_t)b_kr * N + col0 + b_c4);
    storeA(0, a_r0, pa0);
    storeA(0, a_r1, pa1);
    *(uint4*)&Bs_hi[0][b_kr][b_c4] = pbh;
    *(uint4*)&Bs_lo[0][b_kr][b_c4] = pbl;
    __syncthreads();

    const int niter = K >> 4;
    for (int it = 0; it < niter; it++) {
        int st = it & 1;
        bool more = (it + 1 < niter);
        if (more) {
            int kc = (it + 1) << 4;
            pa0 = loadA(kc, a_r0);
            pa1 = loadA(kc, a_r1);
            size_t boff = (size_t)((kc >> 1) + b_kr) * N + col0 + b_c4;
            pbh = *(const uint4*)(Bhi + boff);
            pbl = *(const uint4*)(Blo + boff);
        }
        unsigned ah[2][4], al[2][4];
#pragma unroll
        for (int mt = 0; mt < 2; mt++) {
            int r = warp_m * 32 + mt * 16;
            ah[mt][0] = As_hi[st][r + g][tg];
            ah[mt][1] = As_hi[st][r + g + 8][tg];
            ah[mt][2] = As_hi[st][r + g][4 + tg];
            ah[mt][3] = As_hi[st][r + g + 8][4 + tg];
            al[mt][0] = As_lo[st][r + g][tg];
            al[mt][1] = As_lo[st][r + g + 8][tg];
            al[mt][2] = As_lo[st][r + g][4 + tg];
            al[mt][3] = As_lo[st][r + g + 8][4 + tg];
        }
#pragma unroll
        for (int nt = 0; nt < 8; nt++) {
            int n = warp_n * 64 + nt * 8;
            unsigned bh[2], bl[2];
            bh[0] = Bs_hi[st][tg][n + g];
            bh[1] = Bs_hi[st][4 + tg][n + g];
            bl[0] = Bs_lo[st][tg][n + g];
            bl[1] = Bs_lo[st][4 + tg][n + g];
#pragma unroll
            for (int mt = 0; mt < 2; mt++) {
                mma_bf16(acc[mt][nt], ah[mt], bh);
                mma_bf16(acc[mt][nt], al[mt], bh);
                mma_bf16(acc[mt][nt], ah[mt], bl);
            }
        }
        if (more) {
            int ns = st ^ 1;
            storeA(ns, a_r0, pa0);
            storeA(ns, a_r1, pa1);
            *(uint4*)&Bs_hi[ns][b_kr][b_c4] = pbh;
            *(uint4*)&Bs_lo[ns][b_kr][b_c4] = pbl;
        }
        __syncthreads();
    }

    float cs[8][2], cq[8][2];
#pragma unroll
    for (int nt = 0; nt < 8; nt++) {
        cs[nt][0] = cs[nt][1] = 0.f;
        cq[nt][0] = cq[nt][1] = 0.f;
    }
#pragma unroll
    for (int mt = 0; mt < 2; mt++) {
        int r_lo = row0 + warp_m * 32 + mt * 16 + g;
#pragma unroll
        for (int nt = 0; nt < 8; nt++) {
            int c = col0 + warp_n * 64 + nt * 8 + tg * 2;
            float2 bb = *(const float2*)(bias + c);
            if (r_lo < M) {
                float o0 = acc[mt][nt][0] + bb.x;
                float o1 = acc[mt][nt][1] + bb.y;
                *(float2*)(C + (size_t)r_lo * N + c) = make_float2(o0, o1);
                cs[nt][0] += o0; cq[nt][0] = fmaf(o0, o0, cq[nt][0]);
                cs[nt][1] += o1; cq[nt][1] = fmaf(o1, o1, cq[nt][1]);
            }
            if (r_lo + 8 < M) {
                float o2 = acc[mt][nt][2] + bb.x;
                float o3 = acc[mt][nt][3] + bb.y;
                *(float2*)(C + (size_t)(r_lo + 8) * N + c) = make_float2(o2, o3);
                cs[nt][0] += o2; cq[nt][0] = fmaf(o2, o2, cq[nt][0]);
                cs[nt][1] += o3; cq[nt][1] = fmaf(o3, o3, cq[nt][1]);
            }
        }
    }
#pragma unroll
    for (int nt = 0; nt < 8; nt++) {
#pragma unroll
        for (int c2 = 0; c2 < 2; c2++) {
            float v = cs[nt][c2], q = cq[nt][c2];
            v += __shfl_xor_sync(0xffffffff, v, 16);
            q += __shfl_xor_sync(0xffffffff, q, 16);
            v += __shfl_xor_sync(0xffffffff, v, 8);
            q += __shfl_xor_sync(0xffffffff, q, 8);
            v += __shfl_xor_sync(0xffffffff, v, 4);
            q += __shfl_xor_sync(0xffffffff, q, 4);
            if (g == 0) {
                int cl = warp_n * 64 + nt * 8 + tg * 2 + c2;
                atomicAdd(&s_sum[cl], v);
                atomicAdd(&s_sq[cl], q);
            }
        }
    }
    __syncthreads();
    if (tid < 128) {
        atomicAdd(&gsum[col0 + tid], s_sum[tid]);
        atomicAdd(&gsq[col0 + tid], s_sq[tid]);
    }
}

// ---------------- small fp32 GEMM (VN MLP, 512 rows) ----------------
template <bool PRO>
__global__ void __launch_bounds__(256) k_gemm(
    const float* __restrict__ A, const float* __restrict__ Aadd,
    const float* __restrict__ B, const float* __restrict__ bias,
    const float* __restrict__ scale, const float* __restrict__ shift,
    float* __restrict__ C, float* __restrict__ gsum, float* __restrict__ gsq,
    int M, int K, int N) {
    __shared__ float As[16][68];
    __shared__ float Bs[16][68];
    __shared__ float s_sum[64];
    __shared__ float s_sq[64];
    const int row0 = blockIdx.y * 64;
    const int col0 = blockIdx.x * 64;
    const int tid = threadIdx.x;
    const int tx = tid & 15, ty = tid >> 4;
    if (tid < 64) { s_sum[tid] = 0.f; s_sq[tid] = 0.f; }
    float acc[4][4];
#pragma unroll
    for (int i = 0; i < 4; i++)
#pragma unroll
        for (int j = 0; j < 4; j++) acc[i][j] = 0.f;

    const int ar  = tid >> 2;
    const int akq = (tid & 3) * 4;
    const int bkk = tid >> 4;
    const int bc4 = (tid & 15) * 4;

    for (int k0 = 0; k0 < K; k0 += 16) {
        float4 av = make_float4(0.f, 0.f, 0.f, 0.f);
        int grow = row0 + ar;
        if (grow < M) {
            av = *(const float4*)(A + (size_t)grow * K + k0 + akq);
            if (Aadd) {
                float4 ad = *(const float4*)(Aadd + (size_t)grow * K + k0 + akq);
                av.x += ad.x; av.y += ad.y; av.z += ad.z; av.w += ad.w;
            }
        }
        if (PRO) {
            av.x = fmaxf(fmaf(av.x, scale[k0 + akq + 0], shift[k0 + akq + 0]), 0.f);
            av.y = fmaxf(fmaf(av.y, scale[k0 + akq + 1], shift[k0 + akq + 1]), 0.f);
            av.z = fmaxf(fmaf(av.z, scale[k0 + akq + 2], shift[k0 + akq + 2]), 0.f);
            av.w = fmaxf(fmaf(av.w, scale[k0 + akq + 3], shift[k0 + akq + 3]), 0.f);
        }
        As[akq + 0][ar] = av.x;
        As[akq + 1][ar] = av.y;
        As[akq + 2][ar] = av.z;
        As[akq + 3][ar] = av.w;
        float4 bv = *(const float4*)(B + (size_t)(k0 + bkk) * N + col0 + bc4);
        *(float4*)&Bs[bkk][bc4] = bv;
        __syncthreads();
#pragma unroll
        for (int kk = 0; kk < 16; kk++) {
            float4 a4 = *(const float4*)&As[kk][ty * 4];
            float4 b4 = *(const float4*)&Bs[kk][tx * 4];
            acc[0][0] = fmaf(a4.x, b4.x, acc[0][0]);
            acc[0][1] = fmaf(a4.x, b4.y, acc[0][1]);
            acc[0][2] = fmaf(a4.x, b4.z, acc[0][2]);
            acc[0][3] = fmaf(a4.x, b4.w, acc[0][3]);
            acc[1][0] = fmaf(a4.y, b4.x, acc[1][0]);
            acc[1][1] = fmaf(a4.y, b4.y, acc[1][1]);
            acc[1][2] = fmaf(a4.y, b4.z, acc[1][2]);
            acc[1][3] = fmaf(a4.y, b4.w, acc[1][3]);
            acc[2][0] = fmaf(a4.z, b4.x, acc[2][0]);
            acc[2][1] = fmaf(a4.z, b4.y, acc[2][1]);
            acc[2][2] = fmaf(a4.z, b4.z, acc[2][2]);
            acc[2][3] = fmaf(a4.z, b4.w, acc[2][3]);
            acc[3][0] = fmaf(a4.w, b4.x, acc[3][0]);
            acc[3][1] = fmaf(a4.w, b4.y, acc[3][1]);
            acc[3][2] = fmaf(a4.w, b4.z, acc[3][2]);
            acc[3][3] = fmaf(a4.w, b4.w, acc[3][3]);
        }
        __syncthreads();
    }
    float4 bb = *(const float4*)(bias + col0 + tx * 4);
    float cs[4], cq[4];
#pragma unroll
    for (int j = 0; j < 4; j++) { cs[j] = 0.f; cq[j] = 0.f; }
#pragma unroll
    for (int i = 0; i < 4; i++) {
        int r = row0 + ty * 4 + i;
        if (r < M) {
            float4 o;
            o.x = acc[i][0] + bb.x;
            o.y = acc[i][1] + bb.y;
            o.z = acc[i][2] + bb.z;
            o.w = acc[i][3] + bb.w;
            *(float4*)(C + (size_t)r * N + col0 + tx * 4) = o;
            cs[0] += o.x; cq[0] = fmaf(o.x, o.x, cq[0]);
            cs[1] += o.y; cq[1] = fmaf(o.y, o.y, cq[1]);
            cs[2] += o.z; cq[2] = fmaf(o.z, o.z, cq[2]);
            cs[3] += o.w; cq[3] = fmaf(o.w, o.w, cq[3]);
        }
    }
    if (gsum) {
#pragma unroll
        for (int j = 0; j < 4; j++) {
            atomicAdd(&s_sum[tx * 4 + j], cs[j]);
            atomicAdd(&s_sq[tx * 4 + j], cq[j]);
        }
        __syncthreads();
        if (tid < 64) {
            atomicAdd(&gsum[col0 + tid], s_sum[tid]);
            atomicAdd(&gsq[col0 + tid], s_sq[tid]);
        }
    }
}

// ---------------- BN scale/shift (VN path only) ----------------
__global__ void k_ss(const float* __restrict__ sum, const float* __restrict__ sq,
                     const float* __restrict__ g, const float* __restrict__ b,
                     float invM, float* __restrict__ scale, float* __restrict__ shift) {
    int c = threadIdx.x;
    bn_coef(sum[c], sq[c], g[c], b[c], invM, scale[c], shift[c]);
}

// ---- node-level post with in-block BN coefficient computation ----
__global__ void k_postS(const float* __restrict__ y,
                        const float* __restrict__ sumIn, const float* __restrict__ sqIn,
                        const float* __restrict__ gamma, const float* __restrict__ beta,
                        float invM, __half* __restrict__ posth,
                        const float* __restrict__ vfeat, const int* __restrict__ batch,
                        int do_relu,
                        const int* __restrict__ pbatch, float* __restrict__ poolout) {
    __shared__ float sc[HD], sh[HD];
    int tid = threadIdx.x;
    if (tid < HD)
        bn_coef(sumIn[tid], sqIn[tid], gamma[tid], beta[tid], invM, sc[tid], sh[tid]);
    __syncthreads();
    int i = blockIdx.x * blockDim.x + tid;
    if (i >= NN * (HD / 4)) return;
    int n = i >> 5;
    int c4 = (i & 31) * 4;
    float4 v = *(const float4*)(y + (size_t)n * HD + c4);
    float4 r;
    r.x = fmaf(v.x, sc[c4 + 0], sh[c4 + 0]);
    r.y = fmaf(v.y, sc[c4 + 1], sh[c4 + 1]);
    r.z = fmaf(v.z, sc[c4 + 2], sh[c4 + 2]);
    r.w = fmaf(v.w, sc[c4 + 3], sh[c4 + 3]);
    if (do_relu) {
        r.x = fmaxf(r.x, 0.f); r.y = fmaxf(r.y, 0.f);
        r.z = fmaxf(r.z, 0.f); r.w = fmaxf(r.w, 0.f);
    }
    if (vfeat) {
        int g = __ldg(batch + n);
        float4 vf = *(const float4*)(vfeat + (size_t)g * HD + c4);
        r.x += vf.x; r.y += vf.y; r.z += vf.z; r.w += vf.w;
    }
    if (posth) {
        __half2 p0 = __floats2half2_rn(r.x, r.y);
        __half2 p1 = __floats2half2_rn(r.z, r.w);
        uint2 u = make_uint2(*(unsigned*)&p0, *(unsigned*)&p1);
        *(uint2*)(posth + (size_t)n * HD + c4) = u;
    }
    if (poolout) {
        int g = __ldg(pbatch + n);
        red_add_v4(poolout + (size_t)g * HD + c4, r);
    }
}

// ---- VN-final post (precomputed scale/shift, NG rows) ----
__global__ void k_post(const float* __restrict__ y, const float* __restrict__ scale,
                       const float* __restrict__ shift, float* __restrict__ post, int M) {
    int i = blockIdx.x * blockDim.x + threadIdx.x;
    if (i >= M * (HD / 4)) return;
    int n = i >> 5;
    int c4 = (i & 31) * 4;
    float4 v = *(const float4*)(y + (size_t)n * HD + c4);
    float4 r;
    r.x = fmaxf(fmaf(v.x, scale[c4 + 0], shift[c4 + 0]), 0.f);
    r.y = fmaxf(fmaf(v.y, scale[c4 + 1], shift[c4 + 1]), 0.f);
    r.z = fmaxf(fmaf(v.z, scale[c4 + 2], shift[c4 + 2]), 0.f);
    r.w = fmaxf(fmaf(v.w, scale[c4 + 3], shift[c4 + 3]), 0.f);
    *(float4*)(post + (size_t)n * HD + c4) = r;
}

// ---------------- post(h16) += vfeat[batch] ----------------
__global__ void k_addvn(__half* __restrict__ posth, const float* __restrict__ vfeat,
                        const int* __restrict__ batch) {
    int i = blockIdx.x * blockDim.x + threadIdx.x;
    if (i >= NN * (HD / 4)) return;
    int n = i >> 5;
    int c4 = (i & 31) * 4;
    uint2 u = *(const uint2*)(posth + (size_t)n * HD + c4);
    __half2 h0 = *(__half2*)&u.x;
    __half2 h1 = *(__half2*)&u.y;
    float2 f0 = __half22float2(h0);
    float2 f1 = __half22float2(h1);
    int g = __ldg(batch + n);
    float4 vf = *(const float4*)(vfeat + (size_t)g * HD + c4);
    __half2 p0 = __floats2half2_rn(f0.x + vf.x, f0.y + vf.y);
    __half2 p1 = __floats2half2_rn(f1.x + vf.z, f1.y + vf.w);
    uint2 o = make_uint2(*(unsigned*)&p0, *(unsigned*)&p1);
    *(uint2*)(posth + (size_t)n * HD + c4) = o;
}

__global__ void k_vinit(const float* __restrict__ vn_emb, float* __restrict__ vfeat) {
    int i = blockIdx.x * blockDim.x + threadIdx.x;
    if (i < NG * HD) vfeat[i] = vn_emb[i & (HD - 1)];
}

__global__ void k_count(const int* __restrict__ batch, float* __restrict__ cnt) {
    int i = blockIdx.x * blockDim.x + threadIdx.x;
    if (i < NN) atomicAdd(&cnt[__ldg(batch + i)], 1.f);
}

__global__ void k_div(float* __restrict__ out, const float* __restrict__ cnt) {
    int i = blockIdx.x * blockDim.x + threadIdx.x;
    if (i < NG * HD) out[i] /= fmaxf(cnt[i >> 7], 1.f);
}

// ---------------- host ----------------
extern "C" void kernel_launch(void* const* d_in, const int* in_sizes, int n_in,
                              void* d_out, int out_size) {
    const float* x      = (const float*)d_in[0];
    const int*   ei     = (const int*)d_in[1];
    const int*   batch  = (const int*)d_in[2];
    const float* vn_emb = (const float*)d_in[3];
    const float* c1_W1  = (const float*)d_in[4];
    const float* c1_b1  = (const float*)d_in[5];
    const float* c1_bng = (const float*)d_in[6];
    const float* c1_bnb = (const float*)d_in[7];
    const float* c1_W2  = (const float*)d_in[8];
    const float* c1_b2  = (const float*)d_in[9];
    const float* bn1_g  = (const float*)d_in[10];
    const float* bn1_b  = (const float*)d_in[11];
    const float* cW1    = (const float*)d_in[12];
    const float* cb1    = (const float*)d_in[13];
    const float* cbng   = (const float*)d_in[14];
    const float* cbnb   = (const float*)d_in[15];
    const float* cW2    = (const float*)d_in[16];
    const float* cb2    = (const float*)d_in[17];
    const float* bns_g  = (const float*)d_in[18];
    const float* bns_b  = (const float*)d_in[19];
    const float* vW1    = (const float*)d_in[20];
    const float* vb1    = (const float*)d_in[21];
    const float* vbn1_g = (const float*)d_in[22];
    const float* vbn1_b = (const float*)d_in[23];
    const float* vW2    = (const float*)d_in[24];
    const float* vb2    = (const float*)d_in[25];
    const float* vbn2_g = (const float*)d_in[26];
    const float* vbn2_b = (const float*)d_in[27];
    float* out = (float*)d_out;

    __half* posth;
    unsigned *hhi, *hlo;
    float *t, *y, *stats, *scale, *shift;
    float *vfeat, *pooled, *zmid, *cnt;
    int *deg, *rowptr, *cursor, *eidx, *aux;
    unsigned *whi, *wlo;
    cudaGetSymbolAddress((void**)&posth, g_post);
    cudaGetSymbolAddress((void**)&hhi, g_hhi);
    cudaGetSymbolAddress((void**)&hlo, g_hlo);
    cudaGetSymbolAddress((void**)&t, g_t);
    cudaGetSymbolAddress((void**)&y, g_y);
    cudaGetSymbolAddress((void**)&stats, g_stats);
    cudaGetSymbolAddress((void**)&scale, g_scale);
    cudaGetSymbolAddress((void**)&shift, g_shift);
    cudaGetSymbolAddress((void**)&vfeat, g_vfeat);
    cudaGetSymbolAddress((void**)&pooled, g_pooled);
    cudaGetSymbolAddress((void**)&zmid, g_zmid);
    cudaGetSymbolAddress((void**)&cnt, g_cnt);
    cudaGetSymbolAddress((void**)&deg, g_deg);
    cudaGetSymbolAddress((void**)&rowptr, g_rowptr);
    cudaGetSymbolAddress((void**)&cursor, g_cursor);
    cudaGetSymbolAddress((void**)&eidx, g_eidx);
    cudaGetSymbolAddress((void**)&aux, g_aux);
    cudaGetSymbolAddress((void**)&whi, g_whi);
    cudaGetSymbolAddress((void**)&wlo, g_wlo);

    auto st = [&](int i) { return stats + (size_t)i * HD2; };

    const int* src = ei;
    const int* dst = ei + NE;

    const dim3 bf1_grid(HD2 / 128, (NN + 127) / 128);
    const dim3 bf2_grid(HD / 128, (NN + 127) / 128);
    const int node_blocks = (NN * 32 + 255) / 256;
    const int gat_blocks = (NN / 2 * 32 + 255) / 256;   // 2 nodes per warp
    const int eblk = (NE + 255) / 256;
    const float invN = 1.0f / NN;
    const float invG = 1.0f / NG;

    const int W1E = 64 * HD2;
    const int o_c1W1 = 0, o_c1W2 = W1E, o_cW1_0 = 2 * W1E, o_cW2_0 = 3 * W1E,
              o_cW1_1 = 4 * W1E, o_cW2_1 = 5 * W1E;

    cudaMemsetAsync(stats, 0, 16 * HD2 * sizeof(float), 0);

    k_wsplit_all<<<384, 256>>>(c1_W1, c1_W2, cW1, cW2, whi, wlo);

    // ---- CSR build + x->fp16 conversion ----
    cudaMemsetAsync(deg, 0, NN * sizeof(int), 0);
    k_hist<<<eblk, 256>>>(dst, deg);
    k_x2h<<<node_blocks, 256>>>(x, posth);
    k_scan1<<<SCAN_NB, SCAN_B>>>(deg, rowptr, aux);
    k_scan2<<<1, 128>>>(aux);
    k_scan3<<<SCAN_NB, SCAN_B>>>(rowptr, aux, cursor);
    k_fill<<<eblk, 256>>>(src, dst, cursor, eidx);
    cudaMemsetAsync(cnt, 0, NG * sizeof(float), 0);
    k_count<<<(NN + 255) / 256, 256>>>(batch, cnt);

    // conv MLP: GEMM1 reads pre-split gather planes; GEMM2 reads t with BN prologue
    auto conv_mlp = [&](int sb, int oW1, const float* b1, const float* bng,
                        const float* bnb, int oW2, const float* b2) {
        k_gemm_bfp<<<bf1_grid, 256>>>(hhi, hlo, whi + oW1, wlo + oW1, b1,
                                      t, st(sb), st(sb + 1), NN, HD, HD2);
        k_gemm_bf<<<bf2_grid, 256>>>(t, whi + oW2, wlo + oW2, b2,
                                     st(sb), st(sb + 1), bng, bnb, invN,
                                     y, st(sb + 2), st(sb + 3), NN, HD2, HD);
    };

    // ================= Layer 1 (stats 0..3) =================
    k_gather_h<<<gat_blocks, 256>>>(posth, rowptr, deg, eidx, hhi, hlo);
    conv_mlp(0, o_c1W1, c1_b1, c1_bng, c1_bnb, o_c1W2, c1_b2);
    k_vinit<<<(NG * HD + 255) / 256, 256>>>(vn_emb, vfeat);
    k_postS<<<node_blocks, 256>>>(y, st(2), st(3), bn1_g, bn1_b, invN,
                                  posth, vfeat, batch, 1, nullptr, nullptr);

    // ================= Loop i = 0 (stats 4..7) =================
    k_gather_h<<<gat_blocks, 256>>>(posth, rowptr, deg, eidx, hhi, hlo);
    conv_mlp(4, o_cW1_0, cb1, cbng, cbnb, o_cW2_0, cb2);
    cudaMemsetAsync(pooled, 0, NG * HD * sizeof(float), 0);
    k_postS<<<node_blocks, 256>>>(y, st(6), st(7), bns_g, bns_b, invN,
                                  posth, nullptr, nullptr, 1, batch, pooled);

    // --- virtual node update (stats 12..15) ---
    k_gemm<false><<<dim3(HD2 / 64, NG / 64), 256>>>(pooled, vfeat, vW1, vb1,
                                                    nullptr, nullptr,
                                                    zmid, st(12), st(13), NG, HD, HD2);
    k_ss<<<1, HD2>>>(st(12), st(13), vbn1_g, vbn1_b, invG, scale, shift);
    k_gemm<true><<<dim3(HD / 64, NG / 64), 256>>>(zmid, nullptr, vW2, vb2,
                                                  scale, shift,
                                                  pooled, st(14), st(15), NG, HD2, HD);
    k_ss<<<1, HD>>>(st(14), st(15), vbn2_g, vbn2_b, invG, scale, shift);
    k_post<<<(NG * 32 + 255) / 256, 256>>>(pooled, scale, shift, vfeat, NG);

    // ================= Loop i = 1 (stats 8..11) =================
    k_addvn<<<node_blocks, 256>>>(posth, vfeat, batch);
    k_gather_h<<<gat_blocks, 256>>>(posth, rowptr, deg, eidx, hhi, hlo);
    conv_mlp(8, o_cW1_1, cb1 + HD2, cbng + HD2, cbnb + HD2, o_cW2_1, cb2 + HD);

    // ================= Readout: out = sum_graph bns_1(y) / count ==========
    cudaMemsetAsync(out, 0, NG * HD * sizeof(float), 0);
    k_postS<<<node_blocks, 256>>>(y, st(10), st(11), bns_g + HD, bns_b + HD, invN,
                                  nullptr, nullptr, nullptr, 0, batch, out);
    k_div<<<(NG * HD + 255) / 256, 256>>>(out, cnt);
}

// round 17
// speedup vs baseline: 1.0236x; 1.0236x over previous
#include <cuda_runtime.h>
#include <cuda_bf16.h>
#include <cuda_fp16.h>
#include <cstddef>
#include <cstdint>

#define NN 100000
#define NE 1600000
#define NG 512
#define HD 128
#define HD2 256
#define SCAN_B 1024
#define SCAN_NB ((NN + SCAN_B - 1) / SCAN_B)   // 98

// ---------------- scratch (static device allocations) ----------------
__device__ __half g_post[(size_t)NN * HD];   // fp16 activations (gather input)
__device__ float g_h[(size_t)NN * HD];
__device__ float g_t[(size_t)NN * HD2];
__device__ float g_y[(size_t)NN * HD];
__device__ float g_stats[16][HD2];
__device__ float g_scale[HD2];
__device__ float g_shift[HD2];
__device__ float g_vfeat[NG * HD];
__device__ float g_pooled[NG * HD];
__device__ float g_zmid[NG * HD2];
__device__ float g_cnt[NG];
__device__ int g_deg[NN];
__device__ int g_rowptr[NN];
__device__ int g_cursor[NN];
__device__ int g_eidx[NE];
__device__ int g_aux[SCAN_NB];
// pre-split weights: 6 matrices, packed bf16x2, word index kp*N + n
__device__ unsigned g_whi[98304];
__device__ unsigned g_wlo[98304];

// ---------------- helpers ----------------
__device__ __forceinline__ void red_add_v4(float* p, float4 v) {
    asm volatile("red.global.add.v4.f32 [%0], {%1,%2,%3,%4};"
                 :: "l"(p), "f"(v.x), "f"(v.y), "f"(v.z), "f"(v.w)
                 : "memory");
}

__device__ __forceinline__ void bsplit2(float a, float b, unsigned& h, unsigned& l) {
    unsigned ha = __bfloat16_as_ushort(__float2bfloat16_rn(a));
    unsigned hb = __bfloat16_as_ushort(__float2bfloat16_rn(b));
    float fa = __uint_as_float(ha << 16);
    float fb = __uint_as_float(hb << 16);
    unsigned la = __bfloat16_as_ushort(__float2bfloat16_rn(a - fa));
    unsigned lb = __bfloat16_as_ushort(__float2bfloat16_rn(b - fb));
    h = ha | (hb << 16);
    l = la | (lb << 16);
}

__device__ __forceinline__ void mma_bf16(float* c, const unsigned* a, const unsigned* b) {
    asm volatile(
        "mma.sync.aligned.m16n8k16.row.col.f32.bf16.bf16.f32 "
        "{%0,%1,%2,%3}, {%4,%5,%6,%7}, {%8,%9}, {%0,%1,%2,%3};"
        : "+f"(c[0]), "+f"(c[1]), "+f"(c[2]), "+f"(c[3])
        : "r"(a[0]), "r"(a[1]), "r"(a[2]), "r"(a[3]), "r"(b[0]), "r"(b[1]));
}

__device__ __forceinline__ void bn_coef(float s, float q, float gamma, float beta,
                                        float invM, float& sc, float& sh) {
    float mu = s * invM;
    float var = q * invM - mu * mu;
    float t = gamma * rsqrtf(var + 1e-5f);
    sc = t;
    sh = fmaf(-mu, t, beta);
}

// ================= x -> fp16 conversion (into the post buffer) =================
__global__ void k_x2h(const float* __restrict__ x, __half* __restrict__ xh) {
    int i = blockIdx.x * blockDim.x + threadIdx.x;
    if (i >= NN * (HD / 4)) return;
    float4 v = *(const float4*)(x + (size_t)i * 4);
    __half2 p0 = __floats2half2_rn(v.x, v.y);
    __half2 p1 = __floats2half2_rn(v.z, v.w);
    *(uint2*)(xh + (size_t)i * 4) = make_uint2(*(unsigned*)&p0, *(unsigned*)&p1);
}

// ================= fused weight pre-split (all 6 matrices) =================
__global__ void k_wsplit_all(const float* __restrict__ c1W1, const float* __restrict__ c1W2,
                             const float* __restrict__ cW1, const float* __restrict__ cW2,
                             unsigned* __restrict__ hi, unsigned* __restrict__ lo) {
    int i = blockIdx.x * blockDim.x + threadIdx.x;
    if (i >= 6 * 16384) return;
    int seg = i >> 14;
    int w = i & 16383;
    const float* W;
    int N;
    switch (seg) {
        case 0: W = c1W1; N = HD2; break;
        case 1: W = c1W2; N = HD; break;
        case 2: W = cW1; N = HD2; break;
        case 3: W = cW2; N = HD; break;
        case 4: W = cW1 + (size_t)HD * HD2; N = HD2; break;
        default: W = cW2 + (size_t)HD2 * HD; N = HD; break;
    }
    int kp = w / N, n = w - kp * N;
    float a = W[(size_t)(2 * kp) * N + n];
    float b = W[(size_t)(2 * kp + 1) * N + n];
    bsplit2(a, b, hi[i], lo[i]);
}

// ================= CSR build =================
__global__ void k_hist(const int* __restrict__ dst, int* __restrict__ deg) {
    int e = blockIdx.x * blockDim.x + threadIdx.x;
    if (e < NE) atomicAdd(&deg[__ldg(dst + e)], 1);
}

__global__ void k_scan1(const int* __restrict__ deg, int* __restrict__ rowptr,
                        int* __restrict__ aux) {
    __shared__ int s[SCAN_B];
    int t = threadIdx.x;
    int i = blockIdx.x * SCAN_B + t;
    int v = (i < NN) ? deg[i] : 0;
    s[t] = v;
    __syncthreads();
    for (int off = 1; off < SCAN_B; off <<= 1) {
        int add = (t >= off) ? s[t - off] : 0;
        __syncthreads();
        s[t] += add;
        __syncthreads();
    }
    if (i < NN) rowptr[i] = s[t] - v;
    if (t == SCAN_B - 1) aux[blockIdx.x] = s[t];
}

__global__ void k_scan2(int* __restrict__ aux) {
    __shared__ int s[128];
    int t = threadIdx.x;
    int v = (t < SCAN_NB) ? aux[t] : 0;
    s[t] = v;
    __syncthreads();
    for (int off = 1; off < 128; off <<= 1) {
        int add = (t >= off) ? s[t - off] : 0;
        __syncthreads();
        s[t] += add;
        __syncthreads();
    }
    if (t < SCAN_NB) aux[t] = s[t] - v;
}

__global__ void k_scan3(int* __restrict__ rowptr, const int* __restrict__ aux,
                        int* __restrict__ cursor) {
    int i = blockIdx.x * SCAN_B + threadIdx.x;
    if (i < NN) {
        int v = rowptr[i] + aux[blockIdx.x];
        rowptr[i] = v;
        cursor[i] = v;
    }
}

__global__ void k_fill(const int* __restrict__ src, const int* __restrict__ dst,
                       int* __restrict__ cursor, int* __restrict__ eidx) {
    int e = blockIdx.x * blockDim.x + threadIdx.x;
    if (e >= NE) return;
    int pos = atomicAdd(&cursor[__ldg(dst + e)], 1);
    eidx[pos] = __ldg(src + e);
}

// ====== gather (fp16 input, half-warp per node), fp32 accumulate ======
__global__ void k_gather_h(const __half* __restrict__ in, const int* __restrict__ rowptr,
                           const int* __restrict__ deg, const int* __restrict__ eidx,
                           float* __restrict__ outp) {
    int warp = (blockIdx.x * blockDim.x + threadIdx.x) >> 5;
    if (warp * 2 >= NN) return;               // NN even -> warps are full
    int lane = threadIdx.x & 31;
    int hw = lane >> 4;
    int l16 = lane & 15;
    int n = warp * 2 + hw;

    float acc[8];
    {
        uint4 u = *(const uint4*)(in + (size_t)n * HD + l16 * 8);
        const __half2* hp = (const __half2*)&u;
#pragma unroll
        for (int k = 0; k < 4; k++) {
            float2 f = __half22float2(hp[k]);
            acc[2 * k] = f.x;
            acc[2 * k + 1] = f.y;
        }
    }
    int start = __ldg(rowptr + n);
    int d = __ldg(deg + n);
    int dmax = max(d, __shfl_xor_sync(0xffffffffu, d, 16));
    for (int base = 0; base < dmax; base += 16) {
        int idx = 0;
        if (base + l16 < d) idx = __ldg(eidx + start + base + l16);
        int cnt = min(16, dmax - base);
#pragma unroll 4
        for (int j = 0; j < cnt; j++) {
            int s = __shfl_sync(0xffffffffu, idx, hw * 16 + j);
            if (base + j < d) {
                uint4 u = *(const uint4*)(in + (size_t)s * HD + l16 * 8);
                const __half2* hp = (const __half2*)&u;
#pragma unroll
                for (int k = 0; k < 4; k++) {
                    float2 f = __half22float2(hp[k]);
                    acc[2 * k] += f.x;
                    acc[2 * k + 1] += f.y;
                }
            }
        }
    }
    float* orow = outp + (size_t)n * HD + l16 * 8;
    *(float4*)(orow + 0) = make_float4(acc[0], acc[1], acc[2], acc[3]);
    *(float4*)(orow + 4) = make_float4(acc[4], acc[5], acc[6], acc[7]);
}

// ------- split-BF16 tensor GEMM (3-product) with fused column-stats epilogue -------
template <bool PRO>
__global__ void __launch_bounds__(256, 2) k_gemm_bf(
    const float* __restrict__ A, const unsigned* __restrict__ Bhi,
    const unsigned* __restrict__ Blo, const float* __restrict__ bias,
    const float* __restrict__ sumIn, const float* __restrict__ sqIn,
    const float* __restrict__ gamma, const float* __restrict__ beta, float invM,
    float* __restrict__ C, float* __restrict__ gsum, float* __restrict__ gsq,
    int M, int K, int N) {
    __shared__ unsigned As_hi[2][128][12];
    __shared__ unsigned As_lo[2][128][12];
    __shared__ unsigned Bs_hi[2][8][136];
    __shared__ unsigned Bs_lo[2][8][136];
    __shared__ float s_sum[128];
    __shared__ float s_sq[128];
    __shared__ float sc_s[HD2];
    __shared__ float sh_s[HD2];

    const int tid = threadIdx.x;
    const int wid = tid >> 5;
    const int lane = tid & 31;
    const int g = lane >> 2;
    const int tg = lane & 3;
    const int warp_m = wid >> 1;
    const int warp_n = wid & 1;
    const int row0 = blockIdx.y * 128;
    const int col0 = blockIdx.x * 128;

    if (tid < 128) { s_sum[tid] = 0.f; s_sq[tid] = 0.f; }
    if (PRO) {
        for (int c = tid; c < K; c += 256)
            bn_coef(sumIn[c], sqIn[c], gamma[c], beta[c], invM, sc_s[c], sh_s[c]);
        __syncthreads();
    }

    float acc[2][8][4];
#pragma unroll
    for (int mt = 0; mt < 2; mt++)
#pragma unroll
        for (int nt = 0; nt < 8; nt++)
#pragma unroll
            for (int i = 0; i < 4; i++) acc[mt][nt][i] = 0.f;

    const int a_r0 = tid >> 2;
    const int a_r1 = a_r0 + 64;
    const int a_q = (tid & 3) * 4;
    const int a_kp = (tid & 3) * 2;
    const int b_kr = tid >> 5;
    const int b_c4 = (tid & 31) * 4;

    auto loadA = [&](int kc, int r) -> float4 {
        int grow = row0 + r;
        float4 v = make_float4(0.f, 0.f, 0.f, 0.f);
        if (grow < M) v = *(const float4*)(A + (size_t)grow * K + kc + a_q);
        if (PRO) {
            v.x = fmaxf(fmaf(v.x, sc_s[kc + a_q + 0], sh_s[kc + a_q + 0]), 0.f);
            v.y = fmaxf(fmaf(v.y, sc_s[kc + a_q + 1], sh_s[kc + a_q + 1]), 0.f);
            v.z = fmaxf(fmaf(v.z, sc_s[kc + a_q + 2], sh_s[kc + a_q + 2]), 0.f);
            v.w = fmaxf(fmaf(v.w, sc_s[kc + a_q + 3], sh_s[kc + a_q + 3]), 0.f);
        }
        return v;
    };
    auto storeA = [&](int st, int r, float4 v) {
        unsigned h01, l01, h23, l23;
        bsplit2(v.x, v.y, h01, l01);
        bsplit2(v.z, v.w, h23, l23);
        *(uint2*)&As_hi[st][r][a_kp] = make_uint2(h01, h23);
        *(uint2*)&As_lo[st][r][a_kp] = make_uint2(l01, l23);
    };

    float4 pa0 = loadA(0, a_r0);
    float4 pa1 = loadA(0, a_r1);
    uint4 pbh = *(const uint4*)(Bhi + (size_t)b_kr * N + col0 + b_c4);
    uint4 pbl = *(const uint4*)(Blo + (size_t)b_kr * N + col0 + b_c4);
    storeA(0, a_r0, pa0);
    storeA(0, a_r1, pa1);
    *(uint4*)&Bs_hi[0][b_kr][b_c4] = pbh;
    *(uint4*)&Bs_lo[0][b_kr][b_c4] = pbl;
    __syncthreads();

    const int niter = K >> 4;
    for (int it = 0; it < niter; it++) {
        int st = it & 1;
        bool more = (it + 1 < niter);
        if (more) {
            int kc = (it + 1) << 4;
            pa0 = loadA(kc, a_r0);
            pa1 = loadA(kc, a_r1);
            size_t boff = (size_t)((kc >> 1) + b_kr) * N + col0 + b_c4;
            pbh = *(const uint4*)(Bhi + boff);
            pbl = *(const uint4*)(Blo + boff);
        }
        unsigned ah[2][4], al[2][4];
#pragma unroll
        for (int mt = 0; mt < 2; mt++) {
            int r = warp_m * 32 + mt * 16;
            ah[mt][0] = As_hi[st][r + g][tg];
            ah[mt][1] = As_hi[st][r + g + 8][tg];
            ah[mt][2] = As_hi[st][r + g][4 + tg];
            ah[mt][3] = As_hi[st][r + g + 8][4 + tg];
            al[mt][0] = As_lo[st][r + g][tg];
            al[mt][1] = As_lo[st][r + g + 8][tg];
            al[mt][2] = As_lo[st][r + g][4 + tg];
            al[mt][3] = As_lo[st][r + g + 8][4 + tg];
        }
#pragma unroll
        for (int nt = 0; nt < 8; nt++) {
            int n = warp_n * 64 + nt * 8;
            unsigned bh[2], bl[2];
            bh[0] = Bs_hi[st][tg][n + g];
            bh[1] = Bs_hi[st][4 + tg][n + g];
            bl[0] = Bs_lo[st][tg][n + g];
            bl[1] = Bs_lo[st][4 + tg][n + g];
#pragma unroll
            for (int mt = 0; mt < 2; mt++) {
                mma_bf16(acc[mt][nt], ah[mt], bh);
                mma_bf16(acc[mt][nt], al[mt], bh);
                mma_bf16(acc[mt][nt], ah[mt], bl);
            }
        }
        if (more) {
            int ns = st ^ 1;
            storeA(ns, a_r0, pa0);
            storeA(ns, a_r1, pa1);
            *(uint4*)&Bs_hi[ns][b_kr][b_c4] = pbh;
            *(uint4*)&Bs_lo[ns][b_kr][b_c4] = pbl;
        }
        __syncthreads();
    }

    float cs[8][2], cq[8][2];
#pragma unroll
    for (int nt = 0; nt < 8; nt++) {
        cs[nt][0] = cs[nt][1] = 0.f;
        cq[nt][0] = cq[nt][1] = 0.f;
    }
#pragma unroll
    for (int mt = 0; mt < 2; mt++) {
        int r_lo = row0 + warp_m * 32 + mt * 16 + g;
#pragma unroll
        for (int nt = 0; nt < 8; nt++) {
            int c = col0 + warp_n * 64 + nt * 8 + tg * 2;
            float2 bb = *(const float2*)(bias + c);
            if (r_lo < M) {
                float o0 = acc[mt][nt][0] + bb.x;
                float o1 = acc[mt][nt][1] + bb.y;
                *(float2*)(C + (size_t)r_lo * N + c) = make_float2(o0, o1);
                cs[nt][0] += o0; cq[nt][0] = fmaf(o0, o0, cq[nt][0]);
                cs[nt][1] += o1; cq[nt][1] = fmaf(o1, o1, cq[nt][1]);
            }
            if (r_lo + 8 < M) {
                float o2 = acc[mt][nt][2] + bb.x;
                float o3 = acc[mt][nt][3] + bb.y;
                *(float2*)(C + (size_t)(r_lo + 8) * N + c) = make_float2(o2, o3);
                cs[nt][0] += o2; cq[nt][0] = fmaf(o2, o2, cq[nt][0]);
                cs[nt][1] += o3; cq[nt][1] = fmaf(o3, o3, cq[nt][1]);
            }
        }
    }
#pragma unroll
    for (int nt = 0; nt < 8; nt++) {
#pragma unroll
        for (int c2 = 0; c2 < 2; c2++) {
            float v = cs[nt][c2], q = cq[nt][c2];
            v += __shfl_xor_sync(0xffffffff, v, 16);
            q += __shfl_xor_sync(0xffffffff, q, 16);
            v += __shfl_xor_sync(0xffffffff, v, 8);
            q += __shfl_xor_sync(0xffffffff, q, 8);
            v += __shfl_xor_sync(0xffffffff, v, 4);
            q += __shfl_xor_sync(0xffffffff, q, 4);
            if (g == 0) {
                int cl = warp_n * 64 + nt * 8 + tg * 2 + c2;
                atomicAdd(&s_sum[cl], v);
                atomicAdd(&s_sq[cl], q);
            }
        }
    }
    __syncthreads();
    if (tid < 128) {
        atomicAdd(&gsum[col0 + tid], s_sum[tid]);
        atomicAdd(&gsq[col0 + tid], s_sq[tid]);
    }
}

// ---------------- small fp32 GEMM (VN MLP, 512 rows) ----------------
template <bool PRO>
__global__ void __launch_bounds__(256) k_gemm(
    const float* __restrict__ A, const float* __restrict__ Aadd,
    const float* __restrict__ B, const float* __restrict__ bias,
    const float* __restrict__ scale, const float* __restrict__ shift,
    float* __restrict__ C, float* __restrict__ gsum, float* __restrict__ gsq,
    int M, int K, int N) {
    __shared__ float As[16][68];
    __shared__ float Bs[16][68];
    __shared__ float s_sum[64];
    __shared__ float s_sq[64];
    const int row0 = blockIdx.y * 64;
    const int col0 = blockIdx.x * 64;
    const int tid = threadIdx.x;
    const int tx = tid & 15, ty = tid >> 4;
    if (tid < 64) { s_sum[tid] = 0.f; s_sq[tid] = 0.f; }
    float acc[4][4];
#pragma unroll
    for (int i = 0; i < 4; i++)
#pragma unroll
        for (int j = 0; j < 4; j++) acc[i][j] = 0.f;

    const int ar  = tid >> 2;
    const int akq = (tid & 3) * 4;
    const int bkk = tid >> 4;
    const int bc4 = (tid & 15) * 4;

    for (int k0 = 0; k0 < K; k0 += 16) {
        float4 av = make_float4(0.f, 0.f, 0.f, 0.f);
        int grow = row0 + ar;
        if (grow < M) {
            av = *(const float4*)(A + (size_t)grow * K + k0 + akq);
            if (Aadd) {
                float4 ad = *(const float4*)(Aadd + (size_t)grow * K + k0 + akq);
                av.x += ad.x; av.y += ad.y; av.z += ad.z; av.w += ad.w;
            }
        }
        if (PRO) {
            av.x = fmaxf(fmaf(av.x, scale[k0 + akq + 0], shift[k0 + akq + 0]), 0.f);
            av.y = fmaxf(fmaf(av.y, scale[k0 + akq + 1], shift[k0 + akq + 1]), 0.f);
            av.z = fmaxf(fmaf(av.z, scale[k0 + akq + 2], shift[k0 + akq + 2]), 0.f);
            av.w = fmaxf(fmaf(av.w, scale[k0 + akq + 3], shift[k0 + akq + 3]), 0.f);
        }
        As[akq + 0][ar] = av.x;
        As[akq + 1][ar] = av.y;
        As[akq + 2][ar] = av.z;
        As[akq + 3][ar] = av.w;
        float4 bv = *(const float4*)(B + (size_t)(k0 + bkk) * N + col0 + bc4);
        *(float4*)&Bs[bkk][bc4] = bv;
        __syncthreads();
#pragma unroll
        for (int kk = 0; kk < 16; kk++) {
            float4 a4 = *(const float4*)&As[kk][ty * 4];
            float4 b4 = *(const float4*)&Bs[kk][tx * 4];
            acc[0][0] = fmaf(a4.x, b4.x, acc[0][0]);
            acc[0][1] = fmaf(a4.x, b4.y, acc[0][1]);
            acc[0][2] = fmaf(a4.x, b4.z, acc[0][2]);
            acc[0][3] = fmaf(a4.x, b4.w, acc[0][3]);
            acc[1][0] = fmaf(a4.y, b4.x, acc[1][0]);
            acc[1][1] = fmaf(a4.y, b4.y, acc[1][1]);
            acc[1][2] = fmaf(a4.y, b4.z, acc[1][2]);
            acc[1][3] = fmaf(a4.y, b4.w, acc[1][3]);
            acc[2][0] = fmaf(a4.z, b4.x, acc[2][0]);
            acc[2][1] = fmaf(a4.z, b4.y, acc[2][1]);
            acc[2][2] = fmaf(a4.z, b4.z, acc[2][2]);
            acc[2][3] = fmaf(a4.z, b4.w, acc[2][3]);
            acc[3][0] = fmaf(a4.w, b4.x, acc[3][0]);
            acc[3][1] = fmaf(a4.w, b4.y, acc[3][1]);
            acc[3][2] = fmaf(a4.w, b4.z, acc[3][2]);
            acc[3][3] = fmaf(a4.w, b4.w, acc[3][3]);
        }
        __syncthreads();
    }
    float4 bb = *(const float4*)(bias + col0 + tx * 4);
    float cs[4], cq[4];
#pragma unroll
    for (int j = 0; j < 4; j++) { cs[j] = 0.f; cq[j] = 0.f; }
#pragma unroll
    for (int i = 0; i < 4; i++) {
        int r = row0 + ty * 4 + i;
        if (r < M) {
            float4 o;
            o.x = acc[i][0] + bb.x;
            o.y = acc[i][1] + bb.y;
            o.z = acc[i][2] + bb.z;
            o.w = acc[i][3] + bb.w;
            *(float4*)(C + (size_t)r * N + col0 + tx * 4) = o;
            cs[0] += o.x; cq[0] = fmaf(o.x, o.x, cq[0]);
            cs[1] += o.y; cq[1] = fmaf(o.y, o.y, cq[1]);
            cs[2] += o.z; cq[2] = fmaf(o.z, o.z, cq[2]);
            cs[3] += o.w; cq[3] = fmaf(o.w, o.w, cq[3]);
        }
    }
    if (gsum) {
#pragma unroll
        for (int j = 0; j < 4; j++) {
            atomicAdd(&s_sum[tx * 4 + j], cs[j]);
            atomicAdd(&s_sq[tx * 4 + j], cq[j]);
        }
        __syncthreads();
        if (tid < 64) {
            atomicAdd(&gsum[col0 + tid], s_sum[tid]);
            atomicAdd(&gsq[col0 + tid], s_sq[tid]);
        }
    }
}

// ---------------- BN scale/shift (VN path only) ----------------
__global__ void k_ss(const float* __restrict__ sum, const float* __restrict__ sq,
                     const float* __restrict__ g, const float* __restrict__ b,
                     float invM, float* __restrict__ scale, float* __restrict__ shift) {
    int c = threadIdx.x;
    bn_coef(sum[c], sq[c], g[c], b[c], invM, scale[c], shift[c]);
}

// ---- node-level post with in-block BN coefficient computation ----
// vfeat + batch: per-graph VN row.  vfeat + null batch: uniform row (vn_emb).
__global__ void k_postS(const float* __restrict__ y,
                        const float* __restrict__ sumIn, const float* __restrict__ sqIn,
                        const float* __restrict__ gamma, const float* __restrict__ beta,
                        float invM, __half* __restrict__ posth,
                        const float* __restrict__ vfeat, const int* __restrict__ batch,
                        int do_relu,
                        const int* __restrict__ pbatch, float* __restrict__ poolout) {
    __shared__ float sc[HD], sh[HD];
    int tid = threadIdx.x;
    if (tid < HD)
        bn_coef(sumIn[tid], sqIn[tid], gamma[tid], beta[tid], invM, sc[tid], sh[tid]);
    __syncthreads();
    int i = blockIdx.x * blockDim.x + tid;
    if (i >= NN * (HD / 4)) return;
    int n = i >> 5;
    int c4 = (i & 31) * 4;
    float4 v = *(const float4*)(y + (size_t)n * HD + c4);
    float4 r;
    r.x = fmaf(v.x, sc[c4 + 0], sh[c4 + 0]);
    r.y = fmaf(v.y, sc[c4 + 1], sh[c4 + 1]);
    r.z = fmaf(v.z, sc[c4 + 2], sh[c4 + 2]);
    r.w = fmaf(v.w, sc[c4 + 3], sh[c4 + 3]);
    if (do_relu) {
        r.x = fmaxf(r.x, 0.f); r.y = fmaxf(r.y, 0.f);
        r.z = fmaxf(r.z, 0.f); r.w = fmaxf(r.w, 0.f);
    }
    if (vfeat) {
        const float* vrow = batch ? (vfeat + (size_t)__ldg(batch + n) * HD) : vfeat;
        float4 vf = *(const float4*)(vrow + c4);
        r.x += vf.x; r.y += vf.y; r.z += vf.z; r.w += vf.w;
    }
    if (posth) {
        __half2 p0 = __floats2half2_rn(r.x, r.y);
        __half2 p1 = __floats2half2_rn(r.z, r.w);
        uint2 u = make_uint2(*(unsigned*)&p0, *(unsigned*)&p1);
        *(uint2*)(posth + (size_t)n * HD + c4) = u;
    }
    if (poolout) {
        int g = __ldg(pbatch + n);
        red_add_v4(poolout + (size_t)g * HD + c4, r);
    }
}

// ---- VN-final post (precomputed scale/shift, NG rows) ----
__global__ void k_post(const float* __restrict__ y, const float* __restrict__ scale,
                       const float* __restrict__ shift, float* __restrict__ post, int M) {
    int i = blockIdx.x * blockDim.x + threadIdx.x;
    if (i >= M * (HD / 4)) return;
    int n = i >> 5;
    int c4 = (i & 31) * 4;
    float4 v = *(const float4*)(y + (size_t)n * HD + c4);
    float4 r;
    r.x = fmaxf(fmaf(v.x, scale[c4 + 0], shift[c4 + 0]), 0.f);
    r.y = fmaxf(fmaf(v.y, scale[c4 + 1], shift[c4 + 1]), 0.f);
    r.z = fmaxf(fmaf(v.z, scale[c4 + 2], shift[c4 + 2]), 0.f);
    r.w = fmaxf(fmaf(v.w, scale[c4 + 3], shift[c4 + 3]), 0.f);
    *(float4*)(post + (size_t)n * HD + c4) = r;
}

// ---------------- post(h16) += vfeat[batch] ----------------
__global__ void k_addvn(__half* __restrict__ posth, const float* __restrict__ vfeat,
                        const int* __restrict__ batch) {
    int i = blockIdx.x * blockDim.x + threadIdx.x;
    if (i >= NN * (HD / 4)) return;
    int n = i >> 5;
    int c4 = (i & 31) * 4;
    uint2 u = *(const uint2*)(posth + (size_t)n * HD + c4);
    __half2 h0 = *(__half2*)&u.x;
    __half2 h1 = *(__half2*)&u.y;
    float2 f0 = __half22float2(h0);
    float2 f1 = __half22float2(h1);
    int g = __ldg(batch + n);
    float4 vf = *(const float4*)(vfeat + (size_t)g * HD + c4);
    __half2 p0 = __floats2half2_rn(f0.x + vf.x, f0.y + vf.y);
    __half2 p1 = __floats2half2_rn(f1.x + vf.z, f1.y + vf.w);
    uint2 o = make_uint2(*(unsigned*)&p0, *(unsigned*)&p1);
    *(uint2*)(posth + (size_t)n * HD + c4) = o;
}

__global__ void k_vinit(const float* __restrict__ vn_emb, float* __restrict__ vfeat) {
    int i = blockIdx.x * blockDim.x + threadIdx.x;
    if (i < NG * HD) vfeat[i] = vn_emb[i & (HD - 1)];
}

__global__ void k_count(const int* __restrict__ batch, float* __restrict__ cnt) {
    int i = blockIdx.x * blockDim.x + threadIdx.x;
    if (i < NN) atomicAdd(&cnt[__ldg(batch + i)], 1.f);
}

__global__ void k_div(float* __restrict__ out, const float* __restrict__ cnt) {
    int i = blockIdx.x * blockDim.x + threadIdx.x;
    if (i < NG * HD) out[i] /= fmaxf(cnt[i >> 7], 1.f);
}

// ---------------- host ----------------
extern "C" void kernel_launch(void* const* d_in, const int* in_sizes, int n_in,
                              void* d_out, int out_size) {
    const float* x      = (const float*)d_in[0];
    const int*   ei     = (const int*)d_in[1];
    const int*   batch  = (const int*)d_in[2];
    const float* vn_emb = (const float*)d_in[3];
    const float* c1_W1  = (const float*)d_in[4];
    const float* c1_b1  = (const float*)d_in[5];
    const float* c1_bng = (const float*)d_in[6];
    const float* c1_bnb = (const float*)d_in[7];
    const float* c1_W2  = (const float*)d_in[8];
    const float* c1_b2  = (const float*)d_in[9];
    const float* bn1_g  = (const float*)d_in[10];
    const float* bn1_b  = (const float*)d_in[11];
    const float* cW1    = (const float*)d_in[12];
    const float* cb1    = (const float*)d_in[13];
    const float* cbng   = (const float*)d_in[14];
    const float* cbnb   = (const float*)d_in[15];
    const float* cW2    = (const float*)d_in[16];
    const float* cb2    = (const float*)d_in[17];
    const float* bns_g  = (const float*)d_in[18];
    const float* bns_b  = (const float*)d_in[19];
    const float* vW1    = (const float*)d_in[20];
    const float* vb1    = (const float*)d_in[21];
    const float* vbn1_g = (const float*)d_in[22];
    const float* vbn1_b = (const float*)d_in[23];
    const float* vW2    = (const float*)d_in[24];
    const float* vb2    = (const float*)d_in[25];
    const float* vbn2_g = (const float*)d_in[26];
    const float* vbn2_b = (const float*)d_in[27];
    float* out = (float*)d_out;

    __half* posth;
    float *h, *t, *y, *stats, *scale, *shift;
    float *vfeat, *pooled, *zmid, *cnt;
    int *deg, *rowptr, *cursor, *eidx, *aux;
    unsigned *whi, *wlo;
    cudaGetSymbolAddress((void**)&posth, g_post);
    cudaGetSymbolAddress((void**)&h, g_h);
    cudaGetSymbolAddress((void**)&t, g_t);
    cudaGetSymbolAddress((void**)&y, g_y);
    cudaGetSymbolAddress((void**)&stats, g_stats);
    cudaGetSymbolAddress((void**)&scale, g_scale);
    cudaGetSymbolAddress((void**)&shift, g_shift);
    cudaGetSymbolAddress((void**)&vfeat, g_vfeat);
    cudaGetSymbolAddress((void**)&pooled, g_pooled);
    cudaGetSymbolAddress((void**)&zmid, g_zmid);
    cudaGetSymbolAddress((void**)&cnt, g_cnt);
    cudaGetSymbolAddress((void**)&deg, g_deg);
    cudaGetSymbolAddress((void**)&rowptr, g_rowptr);
    cudaGetSymbolAddress((void**)&cursor, g_cursor);
    cudaGetSymbolAddress((void**)&eidx, g_eidx);
    cudaGetSymbolAddress((void**)&aux, g_aux);
    cudaGetSymbolAddress((void**)&whi, g_whi);
    cudaGetSymbolAddress((void**)&wlo, g_wlo);

    auto st = [&](int i) { return stats + (size_t)i * HD2; };

    const int* src = ei;
    const int* dst = ei + NE;

    const dim3 bf1_grid(HD2 / 128, (NN + 127) / 128);
    const dim3 bf2_grid(HD / 128, (NN + 127) / 128);
    const int node_blocks = (NN * 32 + 255) / 256;
    const int gat_blocks = (NN / 2 * 32 + 255) / 256;   // 2 nodes per warp
    const int eblk = (NE + 255) / 256;
    const float invN = 1.0f / NN;
    const float invG = 1.0f / NG;

    const int W1E = 64 * HD2;
    const int o_c1W1 = 0, o_c1W2 = W1E, o_cW1_0 = 2 * W1E, o_cW2_0 = 3 * W1E,
              o_cW1_1 = 4 * W1E, o_cW2_1 = 5 * W1E;

    cudaMemsetAsync(stats, 0, 16 * HD2 * sizeof(float), 0);

    k_wsplit_all<<<384, 256>>>(c1_W1, c1_W2, cW1, cW2, whi, wlo);

    // ---- CSR build + x->fp16 conversion ----
    cudaMemsetAsync(deg, 0, NN * sizeof(int), 0);
    k_hist<<<eblk, 256>>>(dst, deg);
    k_x2h<<<node_blocks, 256>>>(x, posth);
    k_scan1<<<SCAN_NB, SCAN_B>>>(deg, rowptr, aux);
    k_scan2<<<1, 128>>>(aux);
    k_scan3<<<SCAN_NB, SCAN_B>>>(rowptr, aux, cursor);
    k_fill<<<eblk, 256>>>(src, dst, cursor, eidx);
    cudaMemsetAsync(cnt, 0, NG * sizeof(float), 0);
    k_count<<<(NN + 255) / 256, 256>>>(batch, cnt);

    auto conv_mlp = [&](int sb, int oW1, const float* b1, const float* bng,
                        const float* bnb, int oW2, const float* b2) {
        k_gemm_bf<false><<<bf1_grid, 256>>>(h, whi + oW1, wlo + oW1, b1,
                                            nullptr, nullptr, nullptr, nullptr, 0.f,
                                            t, st(sb), st(sb + 1), NN, HD, HD2);
        k_gemm_bf<true><<<bf2_grid, 256>>>(t, whi + oW2, wlo + oW2, b2,
                                           st(sb), st(sb + 1), bng, bnb, invN,
                                           y, st(sb + 2), st(sb + 3), NN, HD2, HD);
    };

    // ================= Layer 1 (stats 0..3) =================
    k_gather_h<<<gat_blocks, 256>>>(posth, rowptr, deg, eidx, h);
    conv_mlp(0, o_c1W1, c1_b1, c1_bng, c1_bnb, o_c1W2, c1_b2);
    k_vinit<<<(NG * HD + 255) / 256, 256>>>(vn_emb, vfeat);
    // post(fp16) = relu(bn1(y)) + vn_emb   (uniform VN row; batch=null)
    k_postS<<<node_blocks, 256>>>(y, st(2), st(3), bn1_g, bn1_b, invN,
                                  posth, vn_emb, nullptr, 1, nullptr, nullptr);

    // ================= Loop i = 0 (stats 4..7) =================
    k_gather_h<<<gat_blocks, 256>>>(posth, rowptr, deg, eidx, h);
    conv_mlp(4, o_cW1_0, cb1, cbng, cbnb, o_cW2_0, cb2);
    cudaMemsetAsync(pooled, 0, NG * HD * sizeof(float), 0);
    k_postS<<<node_blocks, 256>>>(y, st(6), st(7), bns_g, bns_b, invN,
                                  posth, nullptr, nullptr, 1, batch, pooled);

    // --- virtual node update (stats 12..15) ---
    k_gemm<false><<<dim3(HD2 / 64, NG / 64), 256>>>(pooled, vfeat, vW1, vb1,
                                                    nullptr, nullptr,
                                                    zmid, st(12), st(13), NG, HD, HD2);
    k_ss<<<1, HD2>>>(st(12), st(13), vbn1_g, vbn1_b, invG, scale, shift);
    k_gemm<true><<<dim3(HD / 64, NG / 64), 256>>>(zmid, nullptr, vW2, vb2,
                                                  scale, shift,
                                                  pooled, st(14), st(15), NG, HD2, HD);
    k_ss<<<1, HD>>>(st(14), st(15), vbn2_g, vbn2_b, invG, scale, shift);
    k_post<<<(NG * 32 + 255) / 256, 256>>>(pooled, scale, shift, vfeat, NG);

    // ================= Loop i = 1 (stats 8..11) =================
    k_addvn<<<node_blocks, 256>>>(posth, vfeat, batch);
    k_gather_h<<<gat_blocks, 256>>>(posth, rowptr, deg, eidx, h);
    conv_mlp(8, o_cW1_1, cb1 + HD2, cbng + HD2, cbnb + HD2, o_cW2_1, cb2 + HD);

    // ================= Readout: out = sum_graph bns_1(y) / count ==========
    cudaMemsetAsync(out, 0, NG * HD * sizeof(float), 0);
    k_postS<<<node_blocks, 256>>>(y, st(10), st(11), bns_g + HD, bns_b + HD, invN,
                                  nullptr, nullptr, nullptr, 0, batch, out);
    k_div<<<(NG * HD + 255) / 256, 256>>>(out, cnt);
}